// round 8
// baseline (speedup 1.0000x reference)
#include <cuda_runtime.h>
#include <math.h>

// Problem constants
#define DIRS 2
#define BB   32
#define TT   512
#define DD   512
#define HH   512
#define G4   2048            // 4*H
#define TBM  16384           // T*B
#define NBLK 128             // persistent scan grid (1 block/SM, all co-resident)

static const size_t OUT_HN = (size_t)BB * TT * 2 * HH;   // 16777216
static const size_t OUT_CN = OUT_HN + 4ULL * BB * HH;    // 16842752

typedef unsigned long long ull;

// ---------------- scratch (static device globals; no allocation) ----------------
__device__ __align__(16) float g_xm[(size_t)TBM * 1024];
__device__ __align__(16) float g_xg[(size_t)DIRS * TBM * G4];
__device__ __align__(16) float g_y[(size_t)DIRS * TBM * HH];
__device__ __align__(16) float g_whhT[(size_t)2 * DIRS * HH * HH * 4]; // [layer][dir][hc][k][gate]
__device__ __align__(16) float g_hmT[2][DIRS * HH * BB];               // ping-pong [par][dir][k][b]
__device__ unsigned g_flags[DIRS * 64 * 32];                           // flag per (dir,jt), 128B apart

// init-barrier state (atomic barrier used once per scan launch)
__device__ unsigned g_bar_count = 0;
__device__ unsigned g_bar_gen = 0;

// ---------------- f32x2 helpers ----------------
__device__ __forceinline__ ull pack2(float x, float y) {
    ull r;
    asm("mov.b64 %0, {%1, %2};" : "=l"(r) : "r"(__float_as_uint(x)), "r"(__float_as_uint(y)));
    return r;
}
__device__ __forceinline__ ull splat2(float x) {
    ull r; unsigned u = __float_as_uint(x);
    asm("mov.b64 %0, {%1, %1};" : "=l"(r) : "r"(u));
    return r;
}
__device__ __forceinline__ ull ffma2(ull a, ull b, ull c) {
    ull d;
    asm("fma.rn.f32x2 %0, %1, %2, %3;" : "=l"(d) : "l"(a), "l"(b), "l"(c));
    return d;
}
__device__ __forceinline__ float lo2(ull v) { return __uint_as_float((unsigned)(v & 0xffffffffu)); }
__device__ __forceinline__ float hi2(ull v) { return __uint_as_float((unsigned)(v >> 32)); }

// NaN-safe fast activations (MUFU-based)
__device__ __forceinline__ float fast_sigmoid(float x) {
    return __fdividef(1.0f, 1.0f + __expf(-x));
}
__device__ __forceinline__ float fast_tanh(float x) {
    return 1.0f - __fdividef(2.0f, 1.0f + __expf(2.0f * x));
}

// acquire/release flag ops (gpu scope)
__device__ __forceinline__ unsigned ld_acq(const unsigned* p) {
    unsigned v;
    asm volatile("ld.acquire.gpu.u32 %0, [%1];" : "=r"(v) : "l"(p) : "memory");
    return v;
}
__device__ __forceinline__ void st_rel(unsigned* p, unsigned v) {
    asm volatile("st.release.gpu.u32 [%0], %1;" :: "l"(p), "r"(v) : "memory");
}

// atomic sense-reversing grid barrier: used ONCE per scan launch (init only)
__device__ __forceinline__ void grid_barrier() {
    __syncthreads();
    if (threadIdx.x == 0) {
        __threadfence();
        volatile unsigned* genp = &g_bar_gen;
        unsigned old = *genp;
        unsigned t = atomicAdd(&g_bar_count, 1u);
        if (t == NBLK - 1) {
            g_bar_count = 0;
            __threadfence();
            g_bar_gen = old + 1;
        } else {
            while (*genp == old) {}
        }
        __threadfence();
    }
    __syncthreads();
}

// ---------------- prep kernels ----------------
__global__ void k_mask_in0(const float* __restrict__ x, const float* __restrict__ mask_x) {
    int gid = blockIdx.x * 256 + threadIdx.x;          // < 8388608
    int k = gid & 511; int b = (gid >> 9) & 31; int t = gid >> 14;
    g_xm[gid] = x[((size_t)b * TT + t) * DD + k] * mask_x[b * 512 + k];
}

__global__ void k_build_whhT(const float* __restrict__ w0, const float* __restrict__ w1) {
    int gid = blockIdx.x * 256 + threadIdx.x;          // < 4194304
    int g = gid & 3; int k = (gid >> 2) & 511; int hc = (gid >> 11) & 511;
    int dir = (gid >> 20) & 1; int layer = (gid >> 21) & 1;
    const float* w = layer ? w1 : w0;
    g_whhT[gid] = w[(size_t)dir * G4 * HH + (size_t)(g * HH + hc) * HH + k];
}

__global__ void k_build_in1(const float* __restrict__ mask_out) {
    int gid = blockIdx.x * 256 + threadIdx.x;          // < 16777216
    int j = gid & 1023; int b = (gid >> 10) & 31; int t = gid >> 15;
    int dir = j >> 9; int hc = j & 511;
    g_xm[gid] = g_y[(size_t)dir * TBM * HH + (size_t)(t * BB + b) * HH + hc] * mask_out[b * 1024 + j];
}

// ---------------- input-projection GEMM (both dirs in one launch via blockIdx.z) ----------------
__global__ void __launch_bounds__(256, 2) gemm_nt_bias(
    const float* __restrict__ A, const float* __restrict__ Wbase,
    const float* __restrict__ biasbase, float* __restrict__ Cbase, int K)
{
    __shared__ __align__(16) float As[8][128];
    __shared__ __align__(16) float Ws[8][128];
    const int dir = blockIdx.z;
    const float* W = Wbase + (size_t)dir * G4 * K;
    const float* bias = biasbase + dir * G4;
    float* C = Cbase + (size_t)dir * TBM * G4;

    const int tid = threadIdx.x;
    const int m0 = blockIdx.y * 128;
    const int n0 = blockIdx.x * 128;
    const int lrow = tid >> 1;
    const int lseg = (tid & 1) * 4;
    const float* Ap = A + (size_t)(m0 + lrow) * K + lseg;
    const float* Wp = W + (size_t)(n0 + lrow) * K + lseg;
    const int ty = tid >> 4, tx = tid & 15;

    ull acc[8][4];
#pragma unroll
    for (int i = 0; i < 8; i++) { acc[i][0] = 0; acc[i][1] = 0; acc[i][2] = 0; acc[i][3] = 0; }

    for (int k0 = 0; k0 < K; k0 += 8) {
        float4 av = *(const float4*)(Ap + k0);
        float4 wv = *(const float4*)(Wp + k0);
        __syncthreads();
        As[lseg + 0][lrow] = av.x; As[lseg + 1][lrow] = av.y;
        As[lseg + 2][lrow] = av.z; As[lseg + 3][lrow] = av.w;
        Ws[lseg + 0][lrow] = wv.x; Ws[lseg + 1][lrow] = wv.y;
        Ws[lseg + 2][lrow] = wv.z; Ws[lseg + 3][lrow] = wv.w;
        __syncthreads();
#pragma unroll
        for (int kk = 0; kk < 8; kk++) {
            float4 a0 = *(const float4*)&As[kk][ty * 8];
            float4 a1 = *(const float4*)&As[kk][ty * 8 + 4];
            float4 b0 = *(const float4*)&Ws[kk][tx * 8];
            float4 b1 = *(const float4*)&Ws[kk][tx * 8 + 4];
            ull bp0 = pack2(b0.x, b0.y), bp1 = pack2(b0.z, b0.w);
            ull bp2 = pack2(b1.x, b1.y), bp3 = pack2(b1.z, b1.w);
            float aa[8] = {a0.x, a0.y, a0.z, a0.w, a1.x, a1.y, a1.z, a1.w};
#pragma unroll
            for (int i = 0; i < 8; i++) {
                ull a2 = splat2(aa[i]);
                acc[i][0] = ffma2(a2, bp0, acc[i][0]);
                acc[i][1] = ffma2(a2, bp1, acc[i][1]);
                acc[i][2] = ffma2(a2, bp2, acc[i][2]);
                acc[i][3] = ffma2(a2, bp3, acc[i][3]);
            }
        }
    }
    float bs[8];
#pragma unroll
    for (int j = 0; j < 8; j++) bs[j] = bias[n0 + tx * 8 + j];
#pragma unroll
    for (int i = 0; i < 8; i++) {
        float* Crow = C + (size_t)(m0 + ty * 8 + i) * G4 + n0 + tx * 8;
        float4 v0 = make_float4(lo2(acc[i][0]) + bs[0], hi2(acc[i][0]) + bs[1],
                                lo2(acc[i][1]) + bs[2], hi2(acc[i][1]) + bs[3]);
        float4 v1 = make_float4(lo2(acc[i][2]) + bs[4], hi2(acc[i][2]) + bs[5],
                                lo2(acc[i][3]) + bs[6], hi2(acc[i][3]) + bs[7]);
        *(float4*)(Crow) = v0;
        *(float4*)(Crow + 4) = v1;
    }
}

// ---------------- fused persistent scan, dependency-exact flag sync ----------------
// Block (dir, jt): hc tile [jt*8, jt*8+8), 4 gates, 32 b, full K=512.
// Half-warp kc (16 per block) owns k chunk [kc*32, kc*32+32): those rows of h are
// produced by exactly 4 blocks (jt' = kc*4 .. kc*4+3) -> wait on just those 4 flags.
#define SW_STRIDE 514   // float4 per hc weight row (512 + pad)
#define RED_STRIDE 33   // float4 per (kc,hc) reduction row (32 + pad)

__global__ void __launch_bounds__(256, 1) lstm_scan(int layer, float* __restrict__ out,
                                                    const float* __restrict__ mask_h) {
    extern __shared__ __align__(16) float4 smem4[];
    float4* sw4   = smem4;                       // 8 * 514  float4
    float4* s_hm4 = smem4 + 8 * SW_STRIDE;       // 4096 float4
    float4* red4  = s_hm4 + 4096;                // 128 * 33 float4

    const int bx = blockIdx.x;
    const int tid = threadIdx.x;
    const int dirb = bx >> 6;
    const int jt = bx & 63;

    // phase1 thread identity
    const int kc  = tid >> 4;                    // 0..15 : 32-k chunk
    const int hcp = (tid >> 2) & 3;              // hc pair
    const int bq  = tid & 3;                     // 8-b group
    const int sub = tid & 15;                    // lane within kc half-warp

    // load weight slice into SMEM once
    {
        const float4* whhT4 = (const float4*)g_whhT;
        const size_t rowbase = ((size_t)(layer * 2 + dirb) * 512 + jt * 8) * 512;
        for (int idx = tid; idx < 4096; idx += 256) {
            int r = idx >> 9, k = idx & 511;
            sw4[r * SW_STRIDE + k] = whhT4[rowbase + (size_t)r * 512 + k];
        }
    }

    // phase2 thread identity
    const int hc_local = tid >> 5;
    const int b2 = tid & 31;
    const int hcg = jt * 8 + hc_local;
    const float mh = mask_h[(size_t)layer * 16384 + b2 * 512 + hcg];
    float h_reg = 0.f, c_reg = 0.f;

    // reset own flag + init read buffer h(-1)=0; one atomic barrier makes all visible
    if (tid == 0) *(volatile unsigned*)&g_flags[(dirb * 64 + jt) * 32] = 0u;
    g_hmT[1][dirb * 16384 + hcg * 32 + b2] = 0.f;
    grid_barrier();

    // this half-warp's 4 producer flags (lanes 0..3 poll one each)
    const unsigned* pflag = g_flags + (dirb * 64 + kc * 4 + (sub & 3)) * 32;
    unsigned* myflag = g_flags + (dirb * 64 + jt) * 32;

    const float4* wrow0 = sw4 + (hcp * 2) * SW_STRIDE + kc * 32;
    const float4* wrow1 = wrow0 + SW_STRIDE;
    const float4* hrow  = s_hm4 + kc * 256 + bq * 2;

    for (int s = 0; s < TT; s++) {
        const int t = dirb ? (TT - 1 - s) : s;

        // prefetch xg gates (hidden under wait+GEMM)
        const float* xgb = g_xg + ((size_t)dirb * TBM + (size_t)t * BB + b2) * G4 + hcg;
        float xi = __ldcg(xgb);
        float xf = __ldcg(xgb + HH);
        float xg_ = __ldcg(xgb + 2 * HH);
        float xo = __ldcg(xgb + 3 * HH);

        // wait for only the 4 producers of this kc chunk (lanes 0..3 poll, backoff)
        if (s > 0 && sub < 4) {
            unsigned tgt = (unsigned)s;
            if (ld_acq(pflag) < tgt) {
                do { __nanosleep(40); } while (ld_acq(pflag) < tgt);
            }
        }
        __syncwarp();

        // stage own kc region of h(s-1)
        const float4* hb = (const float4*)(g_hmT[(s + 1) & 1]) + dirb * 4096 + kc * 256;
#pragma unroll
        for (int i = 0; i < 16; i++)
            s_hm4[kc * 256 + i * 16 + sub] = __ldcg(hb + i * 16 + sub);
        __syncwarp();

        // recurrent GEMM over this thread's 32-k chunk
        ull a0[8][2], a1[8][2];
#pragma unroll
        for (int i = 0; i < 8; i++) { a0[i][0] = 0; a0[i][1] = 0; a1[i][0] = 0; a1[i][1] = 0; }

#pragma unroll 4
        for (int kk = 0; kk < 32; kk++) {
            ulonglong2 w0 = *(const ulonglong2*)(wrow0 + kk);   // .x = gates i,f ; .y = g,o
            ulonglong2 w1 = *(const ulonglong2*)(wrow1 + kk);
            float4 hA = hrow[kk * 8];
            float4 hB = hrow[kk * 8 + 1];
            float hv[8] = {hA.x, hA.y, hA.z, hA.w, hB.x, hB.y, hB.z, hB.w};
#pragma unroll
            for (int ib = 0; ib < 8; ib++) {
                ull h2 = splat2(hv[ib]);
                a0[ib][0] = ffma2(h2, w0.x, a0[ib][0]);
                a0[ib][1] = ffma2(h2, w0.y, a0[ib][1]);
                a1[ib][0] = ffma2(h2, w1.x, a1[ib][0]);
                a1[ib][1] = ffma2(h2, w1.y, a1[ib][1]);
            }
        }

        // partials -> padded SMEM reduction buffer
        {
            float4* r0 = red4 + (size_t)(kc * 8 + hcp * 2) * RED_STRIDE + bq * 8;
            float4* r1 = r0 + RED_STRIDE;
#pragma unroll
            for (int ib = 0; ib < 8; ib++) {
                r0[ib] = make_float4(lo2(a0[ib][0]), hi2(a0[ib][0]), lo2(a0[ib][1]), hi2(a0[ib][1]));
                r1[ib] = make_float4(lo2(a1[ib][0]), hi2(a1[ib][0]), lo2(a1[ib][1]), hi2(a1[ib][1]));
            }
        }
        __syncthreads();

        // in-block reduce + pointwise LSTM
        float gi = xi, gf = xf, gg = xg_, go = xo;
#pragma unroll
        for (int k16 = 0; k16 < 16; k16++) {
            float4 v = red4[(size_t)(k16 * 8 + hc_local) * RED_STRIDE + b2];
            gi += v.x; gf += v.y; gg += v.z; go += v.w;
        }
        c_reg = fast_sigmoid(gf) * c_reg + fast_sigmoid(gi) * fast_tanh(gg);
        h_reg = fast_sigmoid(go) * fast_tanh(c_reg);

        // critical-path store, then release-signal once per block
        __stcg(&g_hmT[s & 1][dirb * 16384 + hcg * 32 + b2], h_reg * mh);
        __syncthreads();
        if (tid == 0) st_rel(myflag, (unsigned)(s + 1));

        // off-path output stores after the signal
        if (layer == 0)
            g_y[(size_t)dirb * TBM * HH + ((size_t)t * BB + b2) * HH + hcg] = h_reg;
        else
            out[((size_t)b2 * TT + t) * (2 * HH) + dirb * HH + hcg] = h_reg;
    }

    // final hn / cn from registers: [layer*2+dir][b][h]
    out[OUT_HN + (size_t)layer * 32768 + dirb * 16384 + b2 * 512 + hcg] = h_reg;
    out[OUT_CN + (size_t)layer * 32768 + dirb * 16384 + b2 * 512 + hcg] = c_reg;
}

// ---------------- launcher ----------------
extern "C" void kernel_launch(void* const* d_in, const int* in_sizes, int n_in,
                              void* d_out, int out_size) {
    (void)in_sizes; (void)n_in; (void)out_size;
    const float* x       = (const float*)d_in[0];
    const float* mask_x  = (const float*)d_in[1];
    const float* mask_out= (const float*)d_in[2];
    const float* mask_h  = (const float*)d_in[3];
    const float* w_ih_l0 = (const float*)d_in[4];
    const float* w_hh_l0 = (const float*)d_in[5];
    const float* b_l0    = (const float*)d_in[6];
    const float* w_ih_l1 = (const float*)d_in[7];
    const float* w_hh_l1 = (const float*)d_in[8];
    const float* b_l1    = (const float*)d_in[9];
    float* out = (float*)d_out;

    float *p_xm = nullptr, *p_xg = nullptr;
    cudaGetSymbolAddress((void**)&p_xm, g_xm);
    cudaGetSymbolAddress((void**)&p_xg, g_xg);

    const int scan_smem = (8 * SW_STRIDE + 4096 + 128 * RED_STRIDE) * 16;  // 198912 B
    cudaFuncSetAttribute(lstm_scan, cudaFuncAttributeMaxDynamicSharedMemorySize, scan_smem);

    // our launches #1..#3 before scan0 (#4) -> process launch #6 = scan0 under ncu -s 5
    k_mask_in0<<<8388608 / 256, 256>>>(x, mask_x);                         // #1
    gemm_nt_bias<<<dim3(16, 128, 2), 256>>>(p_xm, w_ih_l0, b_l0, p_xg, DD);// #2 (both dirs)
    k_build_whhT<<<4194304 / 256, 256>>>(w_hh_l0, w_hh_l1);                // #3

    lstm_scan<<<NBLK, 256, scan_smem>>>(0, out, mask_h);                   // #4

    k_build_in1<<<16777216 / 256, 256>>>(mask_out);                        // #5
    gemm_nt_bias<<<dim3(16, 128, 2), 256>>>(p_xm, w_ih_l1, b_l1, p_xg, 2 * HH); // #6
    lstm_scan<<<NBLK, 256, scan_smem>>>(1, out, mask_h);                   // #7
}

// round 9
// speedup vs baseline: 1.2638x; 1.2638x over previous
#include <cuda_runtime.h>
#include <math.h>

// Problem constants
#define DIRS 2
#define BB   32
#define TT   512
#define DD   512
#define HH   512
#define G4   2048            // 4*H
#define TBM  16384           // T*B
#define NBLK 128             // persistent scan grid (1 block/SM, all co-resident)

static const size_t OUT_HN = (size_t)BB * TT * 2 * HH;   // 16777216
static const size_t OUT_CN = OUT_HN + 4ULL * BB * HH;    // 16842752

typedef unsigned long long ull;

// ---------------- scratch (static device globals; no allocation) ----------------
__device__ __align__(16) float g_xm[(size_t)TBM * 1024];
__device__ __align__(16) float g_xg[(size_t)DIRS * TBM * G4];
__device__ __align__(16) float g_y[(size_t)DIRS * TBM * HH];
__device__ __align__(16) float g_whhT[(size_t)2 * DIRS * HH * HH * 4]; // [layer][dir][hc][k][gate]
__device__ __align__(16) float g_hmT[2][DIRS * HH * BB];               // ping-pong [par][dir][k][b]
__device__ unsigned g_flags[DIRS * 64 * 32];                           // flag per (dir,jt), 128B apart

// init-barrier state (atomic barrier used once per scan launch)
__device__ unsigned g_bar_count = 0;
__device__ unsigned g_bar_gen = 0;

// ---------------- f32x2 helpers ----------------
__device__ __forceinline__ ull pack2(float x, float y) {
    ull r;
    asm("mov.b64 %0, {%1, %2};" : "=l"(r) : "r"(__float_as_uint(x)), "r"(__float_as_uint(y)));
    return r;
}
__device__ __forceinline__ ull splat2(float x) {
    ull r; unsigned u = __float_as_uint(x);
    asm("mov.b64 %0, {%1, %1};" : "=l"(r) : "r"(u));
    return r;
}
__device__ __forceinline__ ull ffma2(ull a, ull b, ull c) {
    ull d;
    asm("fma.rn.f32x2 %0, %1, %2, %3;" : "=l"(d) : "l"(a), "l"(b), "l"(c));
    return d;
}
__device__ __forceinline__ float lo2(ull v) { return __uint_as_float((unsigned)(v & 0xffffffffu)); }
__device__ __forceinline__ float hi2(ull v) { return __uint_as_float((unsigned)(v >> 32)); }

// NaN-safe fast activations (MUFU-based)
__device__ __forceinline__ float fast_sigmoid(float x) {
    return __fdividef(1.0f, 1.0f + __expf(-x));
}
__device__ __forceinline__ float fast_tanh(float x) {
    return 1.0f - __fdividef(2.0f, 1.0f + __expf(2.0f * x));
}

// acquire/release flag ops (gpu scope)
__device__ __forceinline__ unsigned ld_acq(const unsigned* p) {
    unsigned v;
    asm volatile("ld.acquire.gpu.u32 %0, [%1];" : "=r"(v) : "l"(p) : "memory");
    return v;
}
__device__ __forceinline__ void st_rel(unsigned* p, unsigned v) {
    asm volatile("st.release.gpu.u32 [%0], %1;" :: "l"(p), "r"(v) : "memory");
}

// tf32 round-to-nearest conversion
__device__ __forceinline__ unsigned cvt_tf32(float f) {
    unsigned u;
    asm("cvt.rna.tf32.f32 %0, %1;" : "=r"(u) : "f"(f));
    return u;
}

// m16n8k8 tf32 MMA (row.col): D += A*B
__device__ __forceinline__ void mma_tf32(float* d, const unsigned* a, const unsigned* b) {
    asm volatile(
        "mma.sync.aligned.m16n8k8.row.col.f32.tf32.tf32.f32 "
        "{%0,%1,%2,%3}, {%4,%5,%6,%7}, {%8,%9}, {%0,%1,%2,%3};"
        : "+f"(d[0]), "+f"(d[1]), "+f"(d[2]), "+f"(d[3])
        : "r"(a[0]), "r"(a[1]), "r"(a[2]), "r"(a[3]), "r"(b[0]), "r"(b[1]));
}

// atomic sense-reversing grid barrier: used ONCE per scan launch (init only)
__device__ __forceinline__ void grid_barrier() {
    __syncthreads();
    if (threadIdx.x == 0) {
        __threadfence();
        volatile unsigned* genp = &g_bar_gen;
        unsigned old = *genp;
        unsigned t = atomicAdd(&g_bar_count, 1u);
        if (t == NBLK - 1) {
            g_bar_count = 0;
            __threadfence();
            g_bar_gen = old + 1;
        } else {
            while (*genp == old) {}
        }
        __threadfence();
    }
    __syncthreads();
}

// ---------------- prep kernels ----------------
__global__ void k_mask_in0(const float* __restrict__ x, const float* __restrict__ mask_x) {
    int gid = blockIdx.x * 256 + threadIdx.x;          // < 8388608
    int k = gid & 511; int b = (gid >> 9) & 31; int t = gid >> 14;
    g_xm[gid] = x[((size_t)b * TT + t) * DD + k] * mask_x[b * 512 + k];
}

__global__ void k_build_whhT(const float* __restrict__ w0, const float* __restrict__ w1) {
    int gid = blockIdx.x * 256 + threadIdx.x;          // < 4194304
    int g = gid & 3; int k = (gid >> 2) & 511; int hc = (gid >> 11) & 511;
    int dir = (gid >> 20) & 1; int layer = (gid >> 21) & 1;
    const float* w = layer ? w1 : w0;
    g_whhT[gid] = w[(size_t)dir * G4 * HH + (size_t)(g * HH + hc) * HH + k];
}

__global__ void k_build_in1(const float* __restrict__ mask_out) {
    int gid = blockIdx.x * 256 + threadIdx.x;          // < 16777216
    int j = gid & 1023; int b = (gid >> 10) & 31; int t = gid >> 15;
    int dir = j >> 9; int hc = j & 511;
    g_xm[gid] = g_y[(size_t)dir * TBM * HH + (size_t)(t * BB + b) * HH + hc] * mask_out[b * 1024 + j];
}

// ---------------- tf32 tensor-core input-projection GEMM ----------------
// C[M=16384, 2048] = A[M,K] * W[2048,K]^T + bias, both dirs via blockIdx.z.
// 128x128 tile, BK=16, 8 warps (4x2), warp tile 32x64, m16n8k8 tf32 mma,
// double-buffered SMEM (stride 20 floats: conflict-free fragment loads).
#define GS 20   // smem floats per row

__global__ void __launch_bounds__(256, 2) gemm_tf32(
    const float* __restrict__ A, const float* __restrict__ Wbase,
    const float* __restrict__ biasbase, float* __restrict__ Cbase, int K)
{
    __shared__ unsigned sA[2][128 * GS];
    __shared__ unsigned sB[2][128 * GS];
    const int dir = blockIdx.z;
    const float* W = Wbase + (size_t)dir * G4 * K;
    const float* bias = biasbase + dir * G4;
    float* C = Cbase + (size_t)dir * TBM * G4;

    const int tid = threadIdx.x;
    const int m0 = blockIdx.y * 128, n0 = blockIdx.x * 128;
    const int warp = tid >> 5, lane = tid & 31;
    const int wm0 = (warp & 3) * 32;     // warp m offset (32 rows)
    const int wn0 = (warp >> 2) * 64;    // warp n offset (64 cols)
    const int grp = lane >> 2, tig = lane & 3;

    // global loaders: thread -> row (tid>>1), 8-float half (tid&1)
    const int ldr = tid >> 1;
    const int ldh = (tid & 1) * 8;
    const float* Ap = A + (size_t)(m0 + ldr) * K + ldh;
    const float* Wp = W + (size_t)(n0 + ldr) * K + ldh;
    unsigned* stA = &sA[0][ldr * GS + ldh];
    unsigned* stB = &sB[0][ldr * GS + ldh];
    const int bufstep = 128 * GS;

    float acc[2][8][4];
#pragma unroll
    for (int i = 0; i < 2; i++)
#pragma unroll
        for (int j = 0; j < 8; j++)
#pragma unroll
            for (int q = 0; q < 4; q++) acc[i][j][q] = 0.f;

    // bias registers for this thread's output columns
    float bsv[8][2];
#pragma unroll
    for (int nt = 0; nt < 8; nt++) {
        int c = n0 + wn0 + nt * 8 + tig * 2;
        bsv[nt][0] = bias[c]; bsv[nt][1] = bias[c + 1];
    }

    // prologue: tile 0 -> buf 0
    {
        float4 a0 = *(const float4*)(Ap), a1 = *(const float4*)(Ap + 4);
        float4 w0 = *(const float4*)(Wp), w1 = *(const float4*)(Wp + 4);
        stA[0] = cvt_tf32(a0.x); stA[1] = cvt_tf32(a0.y); stA[2] = cvt_tf32(a0.z); stA[3] = cvt_tf32(a0.w);
        stA[4] = cvt_tf32(a1.x); stA[5] = cvt_tf32(a1.y); stA[6] = cvt_tf32(a1.z); stA[7] = cvt_tf32(a1.w);
        stB[0] = cvt_tf32(w0.x); stB[1] = cvt_tf32(w0.y); stB[2] = cvt_tf32(w0.z); stB[3] = cvt_tf32(w0.w);
        stB[4] = cvt_tf32(w1.x); stB[5] = cvt_tf32(w1.y); stB[6] = cvt_tf32(w1.z); stB[7] = cvt_tf32(w1.w);
    }
    __syncthreads();

    const int KT = K >> 4;
    for (int kt = 0; kt < KT; kt++) {
        const int buf = kt & 1;
        float4 na0, na1, nw0, nw1;
        const bool more = (kt + 1 < KT);
        if (more) {
            const float* ap = Ap + (kt + 1) * 16;
            const float* wp = Wp + (kt + 1) * 16;
            na0 = *(const float4*)(ap); na1 = *(const float4*)(ap + 4);
            nw0 = *(const float4*)(wp); nw1 = *(const float4*)(wp + 4);
        }

        const unsigned* bA = &sA[0][buf * bufstep];
        const unsigned* bW = &sB[0][buf * bufstep];
#pragma unroll
        for (int ks = 0; ks < 16; ks += 8) {
            unsigned afr[2][4];
#pragma unroll
            for (int mt = 0; mt < 2; mt++) {
                int ra = wm0 + mt * 16 + grp;
                afr[mt][0] = bA[ra * GS + ks + tig];
                afr[mt][1] = bA[(ra + 8) * GS + ks + tig];
                afr[mt][2] = bA[ra * GS + ks + tig + 4];
                afr[mt][3] = bA[(ra + 8) * GS + ks + tig + 4];
            }
#pragma unroll
            for (int nt = 0; nt < 8; nt++) {
                int rb = wn0 + nt * 8 + grp;
                unsigned bfr[2];
                bfr[0] = bW[rb * GS + ks + tig];
                bfr[1] = bW[rb * GS + ks + tig + 4];
                mma_tf32(acc[0][nt], afr[0], bfr);
                mma_tf32(acc[1][nt], afr[1], bfr);
            }
        }

        if (more) {
            unsigned* dA = stA + (buf ^ 1) * bufstep;
            unsigned* dB = stB + (buf ^ 1) * bufstep;
            dA[0] = cvt_tf32(na0.x); dA[1] = cvt_tf32(na0.y); dA[2] = cvt_tf32(na0.z); dA[3] = cvt_tf32(na0.w);
            dA[4] = cvt_tf32(na1.x); dA[5] = cvt_tf32(na1.y); dA[6] = cvt_tf32(na1.z); dA[7] = cvt_tf32(na1.w);
            dB[0] = cvt_tf32(nw0.x); dB[1] = cvt_tf32(nw0.y); dB[2] = cvt_tf32(nw0.z); dB[3] = cvt_tf32(nw0.w);
            dB[4] = cvt_tf32(nw1.x); dB[5] = cvt_tf32(nw1.y); dB[6] = cvt_tf32(nw1.z); dB[7] = cvt_tf32(nw1.w);
            __syncthreads();
        }
    }

    // epilogue: bias add + store
#pragma unroll
    for (int mt = 0; mt < 2; mt++) {
        int r = m0 + wm0 + mt * 16 + grp;
#pragma unroll
        for (int nt = 0; nt < 8; nt++) {
            int c = n0 + wn0 + nt * 8 + tig * 2;
            float2 v0 = make_float2(acc[mt][nt][0] + bsv[nt][0], acc[mt][nt][1] + bsv[nt][1]);
            float2 v1 = make_float2(acc[mt][nt][2] + bsv[nt][0], acc[mt][nt][3] + bsv[nt][1]);
            *(float2*)&C[(size_t)r * G4 + c] = v0;
            *(float2*)&C[(size_t)(r + 8) * G4 + c] = v1;
        }
    }
}

// ---------------- fused persistent scan, dependency-exact flag sync (tight spin) ----------------
#define SW_STRIDE 514   // float4 per hc weight row (512 + pad)
#define RED_STRIDE 33   // float4 per (kc,hc) reduction row (32 + pad)

__global__ void __launch_bounds__(256, 1) lstm_scan(int layer, float* __restrict__ out,
                                                    const float* __restrict__ mask_h) {
    extern __shared__ __align__(16) float4 smem4[];
    float4* sw4   = smem4;                       // 8 * 514  float4
    float4* s_hm4 = smem4 + 8 * SW_STRIDE;       // 4096 float4
    float4* red4  = s_hm4 + 4096;                // 128 * 33 float4

    const int bx = blockIdx.x;
    const int tid = threadIdx.x;
    const int dirb = bx >> 6;
    const int jt = bx & 63;

    const int kc  = tid >> 4;                    // 0..15 : 32-k chunk
    const int hcp = (tid >> 2) & 3;              // hc pair
    const int bq  = tid & 3;                     // 8-b group
    const int sub = tid & 15;                    // lane within kc half-warp

    // load weight slice into SMEM once
    {
        const float4* whhT4 = (const float4*)g_whhT;
        const size_t rowbase = ((size_t)(layer * 2 + dirb) * 512 + jt * 8) * 512;
        for (int idx = tid; idx < 4096; idx += 256) {
            int r = idx >> 9, k = idx & 511;
            sw4[r * SW_STRIDE + k] = whhT4[rowbase + (size_t)r * 512 + k];
        }
    }

    const int hc_local = tid >> 5;
    const int b2 = tid & 31;
    const int hcg = jt * 8 + hc_local;
    const float mh = mask_h[(size_t)layer * 16384 + b2 * 512 + hcg];
    float h_reg = 0.f, c_reg = 0.f;

    if (tid == 0) *(volatile unsigned*)&g_flags[(dirb * 64 + jt) * 32] = 0u;
    g_hmT[1][dirb * 16384 + hcg * 32 + b2] = 0.f;
    grid_barrier();

    const unsigned* pflag = g_flags + (dirb * 64 + kc * 4 + (sub & 3)) * 32;
    unsigned* myflag = g_flags + (dirb * 64 + jt) * 32;

    const float4* wrow0 = sw4 + (hcp * 2) * SW_STRIDE + kc * 32;
    const float4* wrow1 = wrow0 + SW_STRIDE;
    const float4* hrow  = s_hm4 + kc * 256 + bq * 2;

    for (int s = 0; s < TT; s++) {
        const int t = dirb ? (TT - 1 - s) : s;

        // prefetch xg gates (hidden under wait+GEMM)
        const float* xgb = g_xg + ((size_t)dirb * TBM + (size_t)t * BB + b2) * G4 + hcg;
        float xi = __ldcg(xgb);
        float xf = __ldcg(xgb + HH);
        float xg_ = __ldcg(xgb + 2 * HH);
        float xo = __ldcg(xgb + 3 * HH);

        // wait for only the 4 producers of this kc chunk (lanes 0..3, tight spin)
        if (s > 0 && sub < 4) {
            unsigned tgt = (unsigned)s;
            while (ld_acq(pflag) < tgt) {}
        }
        __syncwarp();

        // stage own kc region of h(s-1)
        const float4* hb = (const float4*)(g_hmT[(s + 1) & 1]) + dirb * 4096 + kc * 256;
#pragma unroll
        for (int i = 0; i < 16; i++)
            s_hm4[kc * 256 + i * 16 + sub] = __ldcg(hb + i * 16 + sub);
        __syncwarp();

        // recurrent GEMM over this thread's 32-k chunk
        ull a0[8][2], a1[8][2];
#pragma unroll
        for (int i = 0; i < 8; i++) { a0[i][0] = 0; a0[i][1] = 0; a1[i][0] = 0; a1[i][1] = 0; }

#pragma unroll 4
        for (int kk = 0; kk < 32; kk++) {
            ulonglong2 w0 = *(const ulonglong2*)(wrow0 + kk);   // .x = gates i,f ; .y = g,o
            ulonglong2 w1 = *(const ulonglong2*)(wrow1 + kk);
            float4 hA = hrow[kk * 8];
            float4 hB = hrow[kk * 8 + 1];
            float hv[8] = {hA.x, hA.y, hA.z, hA.w, hB.x, hB.y, hB.z, hB.w};
#pragma unroll
            for (int ib = 0; ib < 8; ib++) {
                ull h2 = splat2(hv[ib]);
                a0[ib][0] = ffma2(h2, w0.x, a0[ib][0]);
                a0[ib][1] = ffma2(h2, w0.y, a0[ib][1]);
                a1[ib][0] = ffma2(h2, w1.x, a1[ib][0]);
                a1[ib][1] = ffma2(h2, w1.y, a1[ib][1]);
            }
        }

        // partials -> padded SMEM reduction buffer
        {
            float4* r0 = red4 + (size_t)(kc * 8 + hcp * 2) * RED_STRIDE + bq * 8;
            float4* r1 = r0 + RED_STRIDE;
#pragma unroll
            for (int ib = 0; ib < 8; ib++) {
                r0[ib] = make_float4(lo2(a0[ib][0]), hi2(a0[ib][0]), lo2(a0[ib][1]), hi2(a0[ib][1]));
                r1[ib] = make_float4(lo2(a1[ib][0]), hi2(a1[ib][0]), lo2(a1[ib][1]), hi2(a1[ib][1]));
            }
        }
        __syncthreads();

        // in-block reduce + pointwise LSTM
        float gi = xi, gf = xf, gg = xg_, go = xo;
#pragma unroll
        for (int k16 = 0; k16 < 16; k16++) {
            float4 v = red4[(size_t)(k16 * 8 + hc_local) * RED_STRIDE + b2];
            gi += v.x; gf += v.y; gg += v.z; go += v.w;
        }
        c_reg = fast_sigmoid(gf) * c_reg + fast_sigmoid(gi) * fast_tanh(gg);
        h_reg = fast_sigmoid(go) * fast_tanh(c_reg);

        __stcg(&g_hmT[s & 1][dirb * 16384 + hcg * 32 + b2], h_reg * mh);
        __syncthreads();
        if (tid == 0) st_rel(myflag, (unsigned)(s + 1));

        // off-path output stores after the signal
        if (layer == 0)
            g_y[(size_t)dirb * TBM * HH + ((size_t)t * BB + b2) * HH + hcg] = h_reg;
        else
            out[((size_t)b2 * TT + t) * (2 * HH) + dirb * HH + hcg] = h_reg;
    }

    out[OUT_HN + (size_t)layer * 32768 + dirb * 16384 + b2 * 512 + hcg] = h_reg;
    out[OUT_CN + (size_t)layer * 32768 + dirb * 16384 + b2 * 512 + hcg] = c_reg;
}

// ---------------- launcher ----------------
extern "C" void kernel_launch(void* const* d_in, const int* in_sizes, int n_in,
                              void* d_out, int out_size) {
    (void)in_sizes; (void)n_in; (void)out_size;
    const float* x       = (const float*)d_in[0];
    const float* mask_x  = (const float*)d_in[1];
    const float* mask_out= (const float*)d_in[2];
    const float* mask_h  = (const float*)d_in[3];
    const float* w_ih_l0 = (const float*)d_in[4];
    const float* w_hh_l0 = (const float*)d_in[5];
    const float* b_l0    = (const float*)d_in[6];
    const float* w_ih_l1 = (const float*)d_in[7];
    const float* w_hh_l1 = (const float*)d_in[8];
    const float* b_l1    = (const float*)d_in[9];
    float* out = (float*)d_out;

    float *p_xm = nullptr, *p_xg = nullptr;
    cudaGetSymbolAddress((void**)&p_xm, g_xm);
    cudaGetSymbolAddress((void**)&p_xg, g_xg);

    const int scan_smem = (8 * SW_STRIDE + 4096 + 128 * RED_STRIDE) * 16;  // 198912 B
    cudaFuncSetAttribute(lstm_scan, cudaFuncAttributeMaxDynamicSharedMemorySize, scan_smem);

    // our launches #1..#3 before scan0 (#4) -> process #6 = scan0 under ncu -s 5
    k_mask_in0<<<8388608 / 256, 256>>>(x, mask_x);                              // #1
    gemm_tf32<<<dim3(16, 128, 2), 256>>>(p_xm, w_ih_l0, b_l0, p_xg, DD);        // #2
    k_build_whhT<<<4194304 / 256, 256>>>(w_hh_l0, w_hh_l1);                     // #3

    lstm_scan<<<NBLK, 256, scan_smem>>>(0, out, mask_h);                        // #4

    k_build_in1<<<16777216 / 256, 256>>>(mask_out);                             // #5
    gemm_tf32<<<dim3(16, 128, 2), 256>>>(p_xm, w_ih_l1, b_l1, p_xg, 2 * HH);    // #6
    lstm_scan<<<NBLK, 256, scan_smem>>>(1, out, mask_h);                        // #7
}